// round 13
// baseline (speedup 1.0000x reference)
#include <cuda_runtime.h>
#include <cuda_bf16.h>
#include <stdint.h>

// GRU persistent scan, warp bf16 MMA (m16n8k16), sm_103-safe ISA.
// R13 = R11 structure (8 warps, K-split, phase-1 x_proj) with the group
// barrier replaced by per-chunk acquire/release dataflow flags (waits
// pipeline under the MMA stream) and warp-0-only fragment publish.
// 128 CTAs x 256 threads, single wave.

#define TT 1024
#define II 256
#define HHID 512
#define NB 128
#define GRID 128
#define NTHREADS 256
#define WSTRIDE 776
#define WLO    (48 * WSTRIDE * 2)
#define WBYTES (48 * WSTRIDE * 2 * 2)      // 148992
#define SCR0B  148992                      // h-GEMM partials, K half 0
#define SCR1B  155328                      // K half 1
#define SCRFB  161664                      // new-h scratch (16 x 33 fp32)
#define BIASB  163776
#define SMEM_BYTES 164032

__device__ unsigned g_xf[(size_t)8 * TT * 16 * 256];     // x A-frags hi/lo
__device__ float    g_xp[(size_t)GRID * TT * 32 * 48];   // x_proj slabs
__device__ uint4    g_hf[2][8 * 32 * 2 * 32];            // h A-frags hi/lo
__device__ __align__(128) int g_flagA[4][32];            // per-chunk flags

__device__ __forceinline__ uint32_t smem_u32(const void* p) {
    uint32_t a;
    asm("{ .reg .u64 t; cvta.to.shared.u64 t, %1; cvt.u32.u64 %0, t; }"
        : "=r"(a) : "l"(p));
    return a;
}
__device__ __forceinline__ int ldacq(const int* p) {
    int v;
    asm volatile("ld.acquire.gpu.global.b32 %0, [%1];" : "=r"(v) : "l"(p) : "memory");
    return v;
}
__device__ __forceinline__ void strel(int* p, int v) {
    asm volatile("st.release.gpu.global.b32 [%0], %1;" :: "l"(p), "r"(v) : "memory");
}
__device__ __forceinline__ void ldsm4(uint32_t a, unsigned& r0, unsigned& r1,
                                      unsigned& r2, unsigned& r3) {
    asm volatile("ldmatrix.sync.aligned.m8n8.x4.shared.b16 {%0,%1,%2,%3}, [%4];"
                 : "=r"(r0), "=r"(r1), "=r"(r2), "=r"(r3) : "r"(a));
}
__device__ __forceinline__ void ldsm2(uint32_t a, unsigned& r0, unsigned& r1) {
    asm volatile("ldmatrix.sync.aligned.m8n8.x2.shared.b16 {%0,%1}, [%2];"
                 : "=r"(r0), "=r"(r1) : "r"(a));
}
__device__ __forceinline__ void mma4(float* d, unsigned a0, unsigned a1,
                                     unsigned a2, unsigned a3,
                                     unsigned b0, unsigned b1) {
    asm volatile("mma.sync.aligned.m16n8k16.row.col.f32.bf16.bf16.f32 "
                 "{%0,%1,%2,%3}, {%4,%5,%6,%7}, {%8,%9}, {%0,%1,%2,%3};"
                 : "+f"(d[0]), "+f"(d[1]), "+f"(d[2]), "+f"(d[3])
                 : "r"(a0), "r"(a1), "r"(a2), "r"(a3), "r"(b0), "r"(b1));
}
__device__ __forceinline__ void cvt_hilo(float2 v, unsigned& hi, unsigned& lo) {
    __nv_bfloat162 h2 = __float22bfloat162_rn(v);
    float2 hf = __bfloat1622float2(h2);
    __nv_bfloat162 l2 = __float22bfloat162_rn(make_float2(v.x - hf.x, v.y - hf.y));
    hi = reinterpret_cast<unsigned&>(h2);
    lo = reinterpret_cast<unsigned&>(l2);
}

// ------- prep: x -> frag layout; h0 -> frag layout (slot 1); zero flags ----
__global__ void __launch_bounds__(256) prep_kernel(
    const float* __restrict__ x, const float* __restrict__ h0) {
    __shared__ float xs[16 * 260];
    const int bx  = blockIdx.x;
    const int tid = threadIdx.x;
    const int w    = tid >> 5;
    const int lane = tid & 31;
    const int rl   = lane >> 2;
    const int c2   = (lane & 3) * 2;
    const int mt  = bx >> 10;
    const int t   = bx & 1023;

    if (bx == 0 && tid < 128) ((int*)g_flagA)[tid] = 0;

    if (bx < 32) {                        // h0 -> g_hf[1]
        int tile = bx * 8 + w;
        int mth = tile >> 5, kc = tile & 31;
        const float* hb = h0 + (size_t)(mth * 16) * HHID + kc * 16;
        unsigned h0r,l0r,h1r,l1r,h2r,l2r,h3r,l3r;
        cvt_hilo(make_float2(hb[rl*HHID+c2],       hb[rl*HHID+c2+1]),       h0r,l0r);
        cvt_hilo(make_float2(hb[(rl+8)*HHID+c2],   hb[(rl+8)*HHID+c2+1]),   h1r,l1r);
        cvt_hilo(make_float2(hb[rl*HHID+c2+8],     hb[rl*HHID+c2+9]),       h2r,l2r);
        cvt_hilo(make_float2(hb[(rl+8)*HHID+c2+8], hb[(rl+8)*HHID+c2+9]),   h3r,l3r);
        g_hf[1][(size_t)tile * 64 + lane]      = make_uint4(h0r,h1r,h2r,h3r);
        g_hf[1][(size_t)tile * 64 + 32 + lane] = make_uint4(l0r,l1r,l2r,l3r);
    }

    #pragma unroll
    for (int it = 0; it < 16; it++)
        xs[it * 260 + tid] = x[(size_t)(mt * 16 + it) * TT * II + (size_t)t * II + tid];
    __syncthreads();

    #pragma unroll
    for (int sub = 0; sub < 2; sub++) {
        int ks = w * 2 + sub;
        int cb = ks * 16 + c2;
        unsigned h0r, l0r, h1r, l1r, h2r, l2r, h3r, l3r;
        cvt_hilo(make_float2(xs[rl * 260 + cb],           xs[rl * 260 + cb + 1]),       h0r, l0r);
        cvt_hilo(make_float2(xs[(rl + 8) * 260 + cb],     xs[(rl + 8) * 260 + cb + 1]), h1r, l1r);
        cvt_hilo(make_float2(xs[rl * 260 + cb + 8],       xs[rl * 260 + cb + 9]),       h2r, l2r);
        cvt_hilo(make_float2(xs[(rl + 8) * 260 + cb + 8], xs[(rl + 8) * 260 + cb + 9]), h3r, l3r);
        unsigned* dst = g_xf + (((size_t)mt * TT + t) * 16 + ks) * 256 + lane * 4;
        *(uint4*)dst         = make_uint4(h0r, h1r, h2r, h3r);
        *(uint4*)(dst + 128) = make_uint4(l0r, l1r, l2r, l3r);
    }
}

__global__ void __launch_bounds__(NTHREADS, 1) gru_mma(
    const float* __restrict__ h0,
    const float* __restrict__ Wih, const float* __restrict__ bih,
    const float* __restrict__ Whh, const float* __restrict__ bhh,
    float* __restrict__ out)
{
    extern __shared__ char smc[];
    const int tid  = threadIdx.x;
    const int lane = tid & 31;
    const int w    = tid >> 5;
    const int grp  = blockIdx.x & 3;
    const int bm0  = grp * 32;
    const int cig  = blockIdx.x >> 2;        // = produced h chunk
    const int j0   = cig * 16;
    const int wm   = (w & 1) * 16;
    const int wn   = ((w >> 1) & 1) * 24;
    const int kw   = w >> 2;                 // phase1: t parity; phase2: K half

    // ---- resident weights, bf16 hi/lo ----
    __nv_bfloat16* Whi_s = (__nv_bfloat16*)smc;
    __nv_bfloat16* Wlo_s = (__nv_bfloat16*)(smc + WLO);
    for (int idx = tid; idx < 48 * 768; idx += NTHREADS) {
        int n = idx / 768, k = idx - n * 768;
        int g = (n >> 4) * HHID + j0 + (n & 15);
        float v = (k < II) ? Wih[g * II + k] : Whh[g * HHID + (k - II)];
        __nv_bfloat16 hi = __float2bfloat16(v);
        Whi_s[n * WSTRIDE + k] = hi;
        Wlo_s[n * WSTRIDE + k] = __float2bfloat16(v - __bfloat162float(hi));
    }
    float* scrH0 = (float*)(smc + SCR0B);
    float* scrH1 = (float*)(smc + SCR1B);
    float* scrF  = (float*)(smc + SCRFB);
    float* bias  = (float*)(smc + BIASB);
    if (tid < 16) {
        int j = j0 + tid;
        bias[tid]      = bih[j]            + bhh[j];
        bias[16 + tid] = bih[HHID + j]     + bhh[HHID + j];
        bias[32 + tid] = bih[2 * HHID + j];
        bias[48 + tid] = bhh[2 * HHID + j];
    }
    __syncthreads();

    const uint32_t sb = smem_u32(smc);
    const int q  = lane & 7;
    const int mi = lane >> 3;
    const uint32_t a4base = sb + (uint32_t)(((wn + 8 * (mi >> 1) + q) * WSTRIDE
                                             + 8 * (mi & 1)) * 2);
    const uint32_t a2base = sb + (uint32_t)(((wn + 16 + q) * WSTRIDE
                                             + 8 * (mi & 1)) * 2);

#define CMPK(AH, AL, KB, ACC) {                                               \
    unsigned h0r,h1r,h2r,h3r,h4r,h5r,l0r,l1r,l2r,l3r,l4r,l5r;                 \
    ldsm4(a4base + (KB), h0r, h1r, h2r, h3r);                                 \
    ldsm2(a2base + (KB), h4r, h5r);                                           \
    ldsm4(a4base + WLO + (KB), l0r, l1r, l2r, l3r);                           \
    ldsm2(a2base + WLO + (KB), l4r, l5r);                                     \
    mma4(ACC[0], (AH).x,(AH).y,(AH).z,(AH).w, h0r, h1r);                      \
    mma4(ACC[1], (AH).x,(AH).y,(AH).z,(AH).w, h2r, h3r);                      \
    mma4(ACC[2], (AH).x,(AH).y,(AH).z,(AH).w, h4r, h5r);                      \
    mma4(ACC[0], (AH).x,(AH).y,(AH).z,(AH).w, l0r, l1r);                      \
    mma4(ACC[1], (AH).x,(AH).y,(AH).z,(AH).w, l2r, l3r);                      \
    mma4(ACC[2], (AH).x,(AH).y,(AH).z,(AH).w, l4r, l5r);                      \
    mma4(ACC[0], (AL).x,(AL).y,(AL).z,(AL).w, h0r, h1r);                      \
    mma4(ACC[1], (AL).x,(AL).y,(AL).z,(AL).w, h2r, h3r);                      \
    mma4(ACC[2], (AL).x,(AL).y,(AL).z,(AL).w, h4r, h5r); }

    float* xpc = g_xp + (size_t)blockIdx.x * TT * (32 * 48);

    // ================= PHASE 1: x_proj for all t (throughput) =============
    {
        const int mt = grp * 2 + (w & 1);
        for (int t = kw; t < TT; t += 2) {
            const uint4* xb = (const uint4*)g_xf
                              + ((size_t)mt * TT + t) * (16 * 64) + lane;
            float acc[3][4] = {{0,0,0,0},{0,0,0,0},{0,0,0,0}};
            #pragma unroll
            for (int ks = 0; ks < 16; ks++) {
                uint4 AH = __ldcg(xb + ks * 64);
                uint4 AL = __ldcg(xb + ks * 64 + 32);
                CMPK(AH, AL, (uint32_t)(ks * 32), acc);
            }
            float* xpt = xpc + (size_t)t * (32 * 48);
            #pragma unroll
            for (int nf = 0; nf < 3; nf++) {
                int n0 = wn + nf * 8 + (lane & 3) * 2;
                int r0 = wm + (lane >> 2);
                *(float2*)(xpt + r0 * 48 + n0)       = make_float2(acc[nf][0], acc[nf][1]);
                *(float2*)(xpt + (r0 + 8) * 48 + n0) = make_float2(acc[nf][2], acc[nf][3]);
            }
        }
    }
    __syncthreads();

    // ================= PHASE 2: latency-critical scan =====================
    const int mg  = (tid >> 4) * 2;
    const int jlg = tid & 15;
    float hprev[2];
    hprev[0] = h0[(bm0 + mg) * HHID + j0 + jlg];
    hprev[1] = h0[(bm0 + mg + 1) * HHID + j0 + jlg];

    const uint32_t HKB = (uint32_t)((II + kw * 256) * 2);
    const int mt2 = grp * 2 + (w & 1);
    int* flg = &g_flagA[grp][kw * 16];            // this warp's 16 chunk flags

    for (int t = 0; t < TT; t++) {
        const int pr = (t + 1) & 1;
        const int pw = t & 1;

        // -- per-chunk gated, pipelined A-frag loads --
        const uint4* hfb = g_hf[pr] + ((size_t)mt2 * 32 + kw * 16) * 64 + lane;
        uint4 bufH[4], bufL[4];
        #pragma unroll
        for (int p = 0; p < 4; p++) {
            while (ldacq(&flg[p]) < t) { }
            bufH[p] = __ldcg(hfb + p * 64);
            bufL[p] = __ldcg(hfb + p * 64 + 32);
        }

        // -- x_proj gate operands (independent; issue early) --
        const float* xpt = xpc + (size_t)t * (32 * 48);
        float xg[2][3];
        #pragma unroll
        for (int i = 0; i < 2; i++) {
            xg[i][0] = xpt[(mg + i) * 48 + jlg];
            xg[i][1] = xpt[(mg + i) * 48 + 16 + jlg];
            xg[i][2] = xpt[(mg + i) * 48 + 32 + jlg];
        }

        float accA[3][4] = {{0,0,0,0},{0,0,0,0},{0,0,0,0}};
        float accB[3][4] = {{0,0,0,0},{0,0,0,0},{0,0,0,0}};
        #pragma unroll
        for (int ks = 0; ks < 16; ks++) {
            uint4 AH = bufH[ks & 3];
            uint4 AL = bufL[ks & 3];
            if (ks + 4 < 16) {
                while (ldacq(&flg[ks + 4]) < t) { }
                bufH[ks & 3] = __ldcg(hfb + (ks + 4) * 64);
                bufL[ks & 3] = __ldcg(hfb + (ks + 4) * 64 + 32);
            }
            if (ks & 1) { CMPK(AH, AL, HKB + (uint32_t)(ks * 32), accB); }
            else        { CMPK(AH, AL, HKB + (uint32_t)(ks * 32), accA); }
        }
        {
            float* scr = kw ? scrH1 : scrH0;
            #pragma unroll
            for (int nf = 0; nf < 3; nf++) {
                int n0 = wn + nf * 8 + (lane & 3) * 2;
                int r0 = wm + (lane >> 2);
                scr[n0 * 33 + r0]           = accA[nf][0] + accB[nf][0];
                scr[(n0 + 1) * 33 + r0]     = accA[nf][1] + accB[nf][1];
                scr[n0 * 33 + r0 + 8]       = accA[nf][2] + accB[nf][2];
                scr[(n0 + 1) * 33 + r0 + 8] = accA[nf][3] + accB[nf][3];
            }
        }
        __syncthreads();

        // -- gates: thread owns (b = bm0+mg+i, j = j0+jlg) --
        #pragma unroll
        for (int i = 0; i < 2; i++) {
            int m = mg + i;
            float hr = scrH0[jlg * 33 + m]        + scrH1[jlg * 33 + m];
            float hz = scrH0[(16 + jlg) * 33 + m] + scrH1[(16 + jlg) * 33 + m];
            float hh = scrH0[(32 + jlg) * 33 + m] + scrH1[(32 + jlg) * 33 + m];
            float r  = 1.f / (1.f + __expf(-(xg[i][0] + hr + bias[jlg])));
            float z  = 1.f / (1.f + __expf(-(xg[i][1] + hz + bias[16 + jlg])));
            float n  = tanhf(xg[i][2] + bias[32 + jlg] + r * (hh + bias[48 + jlg]));
            float hn = (1.f - z) * n + z * hprev[i];
            hprev[i] = hn;
            scrF[jlg * 33 + m] = hn;
            if (t == TT - 1) {
                int o = (bm0 + m) * 2048 + j0 + jlg;
                out[o]                 = r;  out[o + 262144]        = r;
                out[o + 512]           = z;  out[o + 512 + 262144]  = z;
                out[o + 1024]          = n;  out[o + 1024 + 262144] = n;
                out[o + 1536]          = hn; out[o + 1536 + 262144] = hn;
            }
        }
        __syncthreads();

        // -- warp 0 alone: build + publish new-h frags; others race ahead --
        if (w == 0 && t < TT - 1) {
            int rl2 = lane >> 2, c2b = (lane & 3) * 2;
            #pragma unroll
            for (int mtL = 0; mtL < 2; mtL++) {
                int rb = mtL * 16 + rl2;
                unsigned fh0,fl0,fh1,fl1,fh2,fl2,fh3,fl3;
                cvt_hilo(make_float2(scrF[c2b * 33 + rb],       scrF[(c2b + 1) * 33 + rb]),     fh0, fl0);
                cvt_hilo(make_float2(scrF[c2b * 33 + rb + 8],   scrF[(c2b + 1) * 33 + rb + 8]), fh1, fl1);
                cvt_hilo(make_float2(scrF[(c2b + 8) * 33 + rb],     scrF[(c2b + 9) * 33 + rb]),     fh2, fl2);
                cvt_hilo(make_float2(scrF[(c2b + 8) * 33 + rb + 8], scrF[(c2b + 9) * 33 + rb + 8]), fh3, fl3);
                size_t base = ((size_t)(grp * 2 + mtL) * 32 + cig) * 64;
                g_hf[pw][base + lane]      = make_uint4(fh0, fh1, fh2, fh3);
                g_hf[pw][base + 32 + lane] = make_uint4(fl0, fl1, fl2, fl3);
            }
            __threadfence();
            __syncwarp();
            if (lane == 0) strel(&g_flagA[grp][cig], t + 1);
        }
    }
    // flags reset by prep_kernel each launch
}

extern "C" void kernel_launch(void* const* d_in, const int* in_sizes, int n_in,
                              void* d_out, int out_size) {
    const float* x   = (const float*)d_in[0];
    const float* h   = (const float*)d_in[1];
    const float* Wih = (const float*)d_in[2];
    const float* bih = (const float*)d_in[3];
    const float* Whh = (const float*)d_in[4];
    const float* bhh = (const float*)d_in[5];
    float* out = (float*)d_out;

    prep_kernel<<<8192, 256>>>(x, h);

    cudaFuncSetAttribute(gru_mma, cudaFuncAttributeMaxDynamicSharedMemorySize,
                         SMEM_BYTES);
    gru_mma<<<GRID, NTHREADS, SMEM_BYTES>>>(h, Wih, bih, Whh, bhh, out);
}

// round 14
// speedup vs baseline: 2.1214x; 2.1214x over previous
#include <cuda_runtime.h>
#include <cuda_bf16.h>
#include <stdint.h>

// GRU persistent scan, warp bf16 MMA (m16n8k16), sm_103-safe ISA.
// R14 = R11 structure (8 warps, K-split, phase-1 x_proj) with the atomic
// counter barrier replaced by: per-CTA release flags + ONE poller warp per
// CTA (warp-wide 32-flag volatile load) fanning out through an SMEM go-flag.
// h-frags read with __ldcg (explicit L2 coherence). 128 CTAs x 256 thr.

#define TT 1024
#define II 256
#define HHID 512
#define NB 128
#define GRID 128
#define NTHREADS 256
#define WSTRIDE 776
#define WLO    (48 * WSTRIDE * 2)
#define WBYTES (48 * WSTRIDE * 2 * 2)      // 148992
#define SCR0B  148992                      // h-GEMM partials, K half 0
#define SCR1B  155328                      // K half 1
#define SCRFB  161664                      // new-h scratch (16 x 33 fp32)
#define BIASB  163776
#define SMEM_BYTES 164032

__device__ unsigned g_xf[(size_t)8 * TT * 16 * 256];     // x A-frags hi/lo
__device__ float    g_xp[(size_t)GRID * TT * 32 * 48];   // x_proj slabs
__device__ uint4    g_hf[2][8 * 32 * 2 * 32];            // h A-frags hi/lo
__device__ __align__(128) int g_flagA[4][32];            // per-CTA step flags

__device__ __forceinline__ uint32_t smem_u32(const void* p) {
    uint32_t a;
    asm("{ .reg .u64 t; cvta.to.shared.u64 t, %1; cvt.u32.u64 %0, t; }"
        : "=r"(a) : "l"(p));
    return a;
}
__device__ __forceinline__ void ldsm4(uint32_t a, unsigned& r0, unsigned& r1,
                                      unsigned& r2, unsigned& r3) {
    asm volatile("ldmatrix.sync.aligned.m8n8.x4.shared.b16 {%0,%1,%2,%3}, [%4];"
                 : "=r"(r0), "=r"(r1), "=r"(r2), "=r"(r3) : "r"(a));
}
__device__ __forceinline__ void ldsm2(uint32_t a, unsigned& r0, unsigned& r1) {
    asm volatile("ldmatrix.sync.aligned.m8n8.x2.shared.b16 {%0,%1}, [%2];"
                 : "=r"(r0), "=r"(r1) : "r"(a));
}
__device__ __forceinline__ void mma4(float* d, unsigned a0, unsigned a1,
                                     unsigned a2, unsigned a3,
                                     unsigned b0, unsigned b1) {
    asm volatile("mma.sync.aligned.m16n8k16.row.col.f32.bf16.bf16.f32 "
                 "{%0,%1,%2,%3}, {%4,%5,%6,%7}, {%8,%9}, {%0,%1,%2,%3};"
                 : "+f"(d[0]), "+f"(d[1]), "+f"(d[2]), "+f"(d[3])
                 : "r"(a0), "r"(a1), "r"(a2), "r"(a3), "r"(b0), "r"(b1));
}
__device__ __forceinline__ void cvt_hilo(float2 v, unsigned& hi, unsigned& lo) {
    __nv_bfloat162 h2 = __float22bfloat162_rn(v);
    float2 hf = __bfloat1622float2(h2);
    __nv_bfloat162 l2 = __float22bfloat162_rn(make_float2(v.x - hf.x, v.y - hf.y));
    hi = reinterpret_cast<unsigned&>(h2);
    lo = reinterpret_cast<unsigned&>(l2);
}

// ------- prep: x -> frag layout; h0 -> frag layout (slot 1); zero flags ----
__global__ void __launch_bounds__(256) prep_kernel(
    const float* __restrict__ x, const float* __restrict__ h0) {
    __shared__ float xs[16 * 260];
    const int bx  = blockIdx.x;
    const int tid = threadIdx.x;
    const int w    = tid >> 5;
    const int lane = tid & 31;
    const int rl   = lane >> 2;
    const int c2   = (lane & 3) * 2;
    const int mt  = bx >> 10;
    const int t   = bx & 1023;

    if (bx == 0 && tid < 128) ((int*)g_flagA)[tid] = 0;

    if (bx < 32) {                        // h0 -> g_hf[1]
        int tile = bx * 8 + w;
        int mth = tile >> 5, kc = tile & 31;
        const float* hb = h0 + (size_t)(mth * 16) * HHID + kc * 16;
        unsigned h0r,l0r,h1r,l1r,h2r,l2r,h3r,l3r;
        cvt_hilo(make_float2(hb[rl*HHID+c2],       hb[rl*HHID+c2+1]),       h0r,l0r);
        cvt_hilo(make_float2(hb[(rl+8)*HHID+c2],   hb[(rl+8)*HHID+c2+1]),   h1r,l1r);
        cvt_hilo(make_float2(hb[rl*HHID+c2+8],     hb[rl*HHID+c2+9]),       h2r,l2r);
        cvt_hilo(make_float2(hb[(rl+8)*HHID+c2+8], hb[(rl+8)*HHID+c2+9]),   h3r,l3r);
        g_hf[1][(size_t)tile * 64 + lane]      = make_uint4(h0r,h1r,h2r,h3r);
        g_hf[1][(size_t)tile * 64 + 32 + lane] = make_uint4(l0r,l1r,l2r,l3r);
    }

    #pragma unroll
    for (int it = 0; it < 16; it++)
        xs[it * 260 + tid] = x[(size_t)(mt * 16 + it) * TT * II + (size_t)t * II + tid];
    __syncthreads();

    #pragma unroll
    for (int sub = 0; sub < 2; sub++) {
        int ks = w * 2 + sub;
        int cb = ks * 16 + c2;
        unsigned h0r, l0r, h1r, l1r, h2r, l2r, h3r, l3r;
        cvt_hilo(make_float2(xs[rl * 260 + cb],           xs[rl * 260 + cb + 1]),       h0r, l0r);
        cvt_hilo(make_float2(xs[(rl + 8) * 260 + cb],     xs[(rl + 8) * 260 + cb + 1]), h1r, l1r);
        cvt_hilo(make_float2(xs[rl * 260 + cb + 8],       xs[rl * 260 + cb + 9]),       h2r, l2r);
        cvt_hilo(make_float2(xs[(rl + 8) * 260 + cb + 8], xs[(rl + 8) * 260 + cb + 9]), h3r, l3r);
        unsigned* dst = g_xf + (((size_t)mt * TT + t) * 16 + ks) * 256 + lane * 4;
        *(uint4*)dst         = make_uint4(h0r, h1r, h2r, h3r);
        *(uint4*)(dst + 128) = make_uint4(l0r, l1r, l2r, l3r);
    }
}

__global__ void __launch_bounds__(NTHREADS, 1) gru_mma(
    const float* __restrict__ h0,
    const float* __restrict__ Wih, const float* __restrict__ bih,
    const float* __restrict__ Whh, const float* __restrict__ bhh,
    float* __restrict__ out)
{
    extern __shared__ char smc[];
    __shared__ int sh_go;
    const int tid  = threadIdx.x;
    const int lane = tid & 31;
    const int w    = tid >> 5;
    const int grp  = blockIdx.x & 3;
    const int bm0  = grp * 32;
    const int cig  = blockIdx.x >> 2;        // = produced h chunk
    const int j0   = cig * 16;
    const int wm   = (w & 1) * 16;
    const int wn   = ((w >> 1) & 1) * 24;
    const int kw   = w >> 2;                 // phase1: t parity; phase2: K half

    if (tid == 0) sh_go = 0;

    // ---- resident weights, bf16 hi/lo ----
    __nv_bfloat16* Whi_s = (__nv_bfloat16*)smc;
    __nv_bfloat16* Wlo_s = (__nv_bfloat16*)(smc + WLO);
    for (int idx = tid; idx < 48 * 768; idx += NTHREADS) {
        int n = idx / 768, k = idx - n * 768;
        int g = (n >> 4) * HHID + j0 + (n & 15);
        float v = (k < II) ? Wih[g * II + k] : Whh[g * HHID + (k - II)];
        __nv_bfloat16 hi = __float2bfloat16(v);
        Whi_s[n * WSTRIDE + k] = hi;
        Wlo_s[n * WSTRIDE + k] = __float2bfloat16(v - __bfloat162float(hi));
    }
    float* scrH0 = (float*)(smc + SCR0B);
    float* scrH1 = (float*)(smc + SCR1B);
    float* scrF  = (float*)(smc + SCRFB);
    float* bias  = (float*)(smc + BIASB);
    if (tid < 16) {
        int j = j0 + tid;
        bias[tid]      = bih[j]            + bhh[j];
        bias[16 + tid] = bih[HHID + j]     + bhh[HHID + j];
        bias[32 + tid] = bih[2 * HHID + j];
        bias[48 + tid] = bhh[2 * HHID + j];
    }
    __syncthreads();

    const uint32_t sb = smem_u32(smc);
    const int q  = lane & 7;
    const int mi = lane >> 3;
    const uint32_t a4base = sb + (uint32_t)(((wn + 8 * (mi >> 1) + q) * WSTRIDE
                                             + 8 * (mi & 1)) * 2);
    const uint32_t a2base = sb + (uint32_t)(((wn + 16 + q) * WSTRIDE
                                             + 8 * (mi & 1)) * 2);

#define CMPK(AH, AL, KB, ACC) {                                               \
    unsigned h0r,h1r,h2r,h3r,h4r,h5r,l0r,l1r,l2r,l3r,l4r,l5r;                 \
    ldsm4(a4base + (KB), h0r, h1r, h2r, h3r);                                 \
    ldsm2(a2base + (KB), h4r, h5r);                                           \
    ldsm4(a4base + WLO + (KB), l0r, l1r, l2r, l3r);                           \
    ldsm2(a2base + WLO + (KB), l4r, l5r);                                     \
    mma4(ACC[0], (AH).x,(AH).y,(AH).z,(AH).w, h0r, h1r);                      \
    mma4(ACC[1], (AH).x,(AH).y,(AH).z,(AH).w, h2r, h3r);                      \
    mma4(ACC[2], (AH).x,(AH).y,(AH).z,(AH).w, h4r, h5r);                      \
    mma4(ACC[0], (AH).x,(AH).y,(AH).z,(AH).w, l0r, l1r);                      \
    mma4(ACC[1], (AH).x,(AH).y,(AH).z,(AH).w, l2r, l3r);                      \
    mma4(ACC[2], (AH).x,(AH).y,(AH).z,(AH).w, l4r, l5r);                      \
    mma4(ACC[0], (AL).x,(AL).y,(AL).z,(AL).w, h0r, h1r);                      \
    mma4(ACC[1], (AL).x,(AL).y,(AL).z,(AL).w, h2r, h3r);                      \
    mma4(ACC[2], (AL).x,(AL).y,(AL).z,(AL).w, h4r, h5r); }

    float* xpc = g_xp + (size_t)blockIdx.x * TT * (32 * 48);

    // ================= PHASE 1: x_proj for all t (throughput) =============
    {
        const int mt = grp * 2 + (w & 1);
        for (int t = kw; t < TT; t += 2) {
            const uint4* xb = (const uint4*)g_xf
                              + ((size_t)mt * TT + t) * (16 * 64) + lane;
            float acc[3][4] = {{0,0,0,0},{0,0,0,0},{0,0,0,0}};
            #pragma unroll
            for (int ks = 0; ks < 16; ks++) {
                uint4 AH = xb[ks * 64];
                uint4 AL = xb[ks * 64 + 32];
                CMPK(AH, AL, (uint32_t)(ks * 32), acc);
            }
            float* xpt = xpc + (size_t)t * (32 * 48);
            #pragma unroll
            for (int nf = 0; nf < 3; nf++) {
                int n0 = wn + nf * 8 + (lane & 3) * 2;
                int r0 = wm + (lane >> 2);
                *(float2*)(xpt + r0 * 48 + n0)       = make_float2(acc[nf][0], acc[nf][1]);
                *(float2*)(xpt + (r0 + 8) * 48 + n0) = make_float2(acc[nf][2], acc[nf][3]);
            }
        }
    }
    __syncthreads();

    // ================= PHASE 2: latency-critical scan =====================
    const int mg  = (tid >> 4) * 2;
    const int jlg = tid & 15;
    float hprev[2];
    hprev[0] = h0[(bm0 + mg) * HHID + j0 + jlg];
    hprev[1] = h0[(bm0 + mg + 1) * HHID + j0 + jlg];

    const uint32_t HKB = (uint32_t)((II + kw * 256) * 2);
    const int mt2 = grp * 2 + (w & 1);
    volatile int* fl = (volatile int*)&g_flagA[grp][0];
    volatile int* go = (volatile int*)&sh_go;

    for (int t = 0; t < TT; t++) {
        const int pr = (t + 1) & 1;
        const int pw = t & 1;

        // -- x_proj gate operands first (h-independent; hide under spin) --
        const float* xpt = xpc + (size_t)t * (32 * 48);
        float xg[2][3];
        #pragma unroll
        for (int i = 0; i < 2; i++) {
            xg[i][0] = xpt[(mg + i) * 48 + jlg];
            xg[i][1] = xpt[(mg + i) * 48 + 16 + jlg];
            xg[i][2] = xpt[(mg + i) * 48 + 32 + jlg];
        }

        // -- readiness: warp 7 polls the 32 group flags, fans out via SMEM --
        if (w == 7) {
            int v;
            do { v = fl[lane]; } while (__any_sync(0xFFFFFFFFu, v < t));
            if (lane == 0) *go = t;
        }
        while (*go < t) { }

        // -- h A-frags: L2-coherent loads, pipelined depth 4 --
        const uint4* hfb = g_hf[pr] + ((size_t)mt2 * 32 + kw * 16) * 64 + lane;
        uint4 bufH[4], bufL[4];
        #pragma unroll
        for (int p = 0; p < 4; p++) {
            bufH[p] = __ldcg(hfb + p * 64);
            bufL[p] = __ldcg(hfb + p * 64 + 32);
        }
        float accA[3][4] = {{0,0,0,0},{0,0,0,0},{0,0,0,0}};
        float accB[3][4] = {{0,0,0,0},{0,0,0,0},{0,0,0,0}};
        #pragma unroll
        for (int ks = 0; ks < 16; ks++) {
            uint4 AH = bufH[ks & 3];
            uint4 AL = bufL[ks & 3];
            if (ks + 4 < 16) {
                bufH[ks & 3] = __ldcg(hfb + (ks + 4) * 64);
                bufL[ks & 3] = __ldcg(hfb + (ks + 4) * 64 + 32);
            }
            if (ks & 1) { CMPK(AH, AL, HKB + (uint32_t)(ks * 32), accB); }
            else        { CMPK(AH, AL, HKB + (uint32_t)(ks * 32), accA); }
        }
        {
            float* scr = kw ? scrH1 : scrH0;
            #pragma unroll
            for (int nf = 0; nf < 3; nf++) {
                int n0 = wn + nf * 8 + (lane & 3) * 2;
                int r0 = wm + (lane >> 2);
                scr[n0 * 33 + r0]           = accA[nf][0] + accB[nf][0];
                scr[(n0 + 1) * 33 + r0]     = accA[nf][1] + accB[nf][1];
                scr[n0 * 33 + r0 + 8]       = accA[nf][2] + accB[nf][2];
                scr[(n0 + 1) * 33 + r0 + 8] = accA[nf][3] + accB[nf][3];
            }
        }
        __syncthreads();

        // -- gates: thread owns (b = bm0+mg+i, j = j0+jlg) --
        #pragma unroll
        for (int i = 0; i < 2; i++) {
            int m = mg + i;
            float hr = scrH0[jlg * 33 + m]        + scrH1[jlg * 33 + m];
            float hz = scrH0[(16 + jlg) * 33 + m] + scrH1[(16 + jlg) * 33 + m];
            float hh = scrH0[(32 + jlg) * 33 + m] + scrH1[(32 + jlg) * 33 + m];
            float r  = 1.f / (1.f + __expf(-(xg[i][0] + hr + bias[jlg])));
            float z  = 1.f / (1.f + __expf(-(xg[i][1] + hz + bias[16 + jlg])));
            float n  = tanhf(xg[i][2] + bias[32 + jlg] + r * (hh + bias[48 + jlg]));
            float hn = (1.f - z) * n + z * hprev[i];
            hprev[i] = hn;
            scrF[jlg * 33 + m] = hn;
            if (t == TT - 1) {
                int o = (bm0 + m) * 2048 + j0 + jlg;
                out[o]                 = r;  out[o + 262144]        = r;
                out[o + 512]           = z;  out[o + 512 + 262144]  = z;
                out[o + 1024]          = n;  out[o + 1024 + 262144] = n;
                out[o + 1536]          = hn; out[o + 1536 + 262144] = hn;
            }
        }
        __syncthreads();

        // -- warps 0-1: build + publish new-h frags, release flag --
        if (t < TT - 1 && tid < 64) {
            int mtL = tid >> 5, ln = tid & 31;
            int rl2 = ln >> 2, c2b = (ln & 3) * 2;
            int rb  = mtL * 16 + rl2;
            unsigned fh0,fl0,fh1,fl1,fh2,fl2,fh3,fl3;
            cvt_hilo(make_float2(scrF[c2b * 33 + rb],       scrF[(c2b + 1) * 33 + rb]),     fh0, fl0);
            cvt_hilo(make_float2(scrF[c2b * 33 + rb + 8],   scrF[(c2b + 1) * 33 + rb + 8]), fh1, fl1);
            cvt_hilo(make_float2(scrF[(c2b + 8) * 33 + rb],     scrF[(c2b + 9) * 33 + rb]),     fh2, fl2);
            cvt_hilo(make_float2(scrF[(c2b + 8) * 33 + rb + 8], scrF[(c2b + 9) * 33 + rb + 8]), fh3, fl3);
            size_t base = ((size_t)(grp * 2 + mtL) * 32 + cig) * 64;
            g_hf[pw][base + ln]      = make_uint4(fh0, fh1, fh2, fh3);
            g_hf[pw][base + 32 + ln] = make_uint4(fl0, fl1, fl2, fl3);
            __threadfence();
            asm volatile("bar.sync 2, 64;" ::: "memory");
            if (tid == 0) ((volatile int*)&g_flagA[grp][cig])[0] = t + 1;
        }
    }
    // flags reset by prep_kernel each launch
}

extern "C" void kernel_launch(void* const* d_in, const int* in_sizes, int n_in,
                              void* d_out, int out_size) {
    const float* x   = (const float*)d_in[0];
    const float* h   = (const float*)d_in[1];
    const float* Wih = (const float*)d_in[2];
    const float* bih = (const float*)d_in[3];
    const float* Whh = (const float*)d_in[4];
    const float* bhh = (const float*)d_in[5];
    float* out = (float*)d_out;

    prep_kernel<<<8192, 256>>>(x, h);

    cudaFuncSetAttribute(gru_mma, cudaFuncAttributeMaxDynamicSharedMemorySize,
                         SMEM_BYTES);
    gru_mma<<<GRID, NTHREADS, SMEM_BYTES>>>(h, Wih, bih, Whh, bhh, out);
}

// round 15
// speedup vs baseline: 3.2647x; 1.5389x over previous
#include <cuda_runtime.h>
#include <cuda_bf16.h>
#include <stdint.h>

// GRU persistent scan, warp bf16 MMA (m16n8k16), sm_103-safe ISA.
// R15 = R14 exchange/publish structure, but x_proj is folded INTO the scan:
// each step, after publishing h[t+1], the same 8 warps compute the x_proj
// tile for t+8 (2-way K-split, two partial slabs summed at gate time).
// The separate phase-1 is gone; x work hides the flag/L2 exchange gap.
// 128 CTAs x 256 threads, single wave.

#define TT 1024
#define II 256
#define HHID 512
#define NB 128
#define GRID 128
#define NTHREADS 256
#define WSTRIDE 776
#define WLO    (48 * WSTRIDE * 2)
#define WBYTES (48 * WSTRIDE * 2 * 2)      // 148992
#define SCR0B  148992                      // h-GEMM partials, K half 0
#define SCR1B  155328                      // K half 1
#define SCRFB  161664                      // new-h scratch (16 x 33 fp32)
#define BIASB  163776
#define SMEM_BYTES 164032
#define XLOOK 8                            // x_proj lookahead (steps)

__device__ unsigned g_xf[(size_t)8 * TT * 16 * 256];     // x A-frags hi/lo
__device__ float    g_xp[(size_t)GRID * 2 * TT * 1536];  // x_proj K-half slabs
__device__ uint4    g_hf[2][8 * 32 * 2 * 32];            // h A-frags hi/lo
__device__ __align__(128) int g_flagA[4][32];            // per-CTA step flags

__device__ __forceinline__ uint32_t smem_u32(const void* p) {
    uint32_t a;
    asm("{ .reg .u64 t; cvta.to.shared.u64 t, %1; cvt.u32.u64 %0, t; }"
        : "=r"(a) : "l"(p));
    return a;
}
__device__ __forceinline__ void ldsm4(uint32_t a, unsigned& r0, unsigned& r1,
                                      unsigned& r2, unsigned& r3) {
    asm volatile("ldmatrix.sync.aligned.m8n8.x4.shared.b16 {%0,%1,%2,%3}, [%4];"
                 : "=r"(r0), "=r"(r1), "=r"(r2), "=r"(r3) : "r"(a));
}
__device__ __forceinline__ void ldsm2(uint32_t a, unsigned& r0, unsigned& r1) {
    asm volatile("ldmatrix.sync.aligned.m8n8.x2.shared.b16 {%0,%1}, [%2];"
                 : "=r"(r0), "=r"(r1) : "r"(a));
}
__device__ __forceinline__ void mma4(float* d, unsigned a0, unsigned a1,
                                     unsigned a2, unsigned a3,
                                     unsigned b0, unsigned b1) {
    asm volatile("mma.sync.aligned.m16n8k16.row.col.f32.bf16.bf16.f32 "
                 "{%0,%1,%2,%3}, {%4,%5,%6,%7}, {%8,%9}, {%0,%1,%2,%3};"
                 : "+f"(d[0]), "+f"(d[1]), "+f"(d[2]), "+f"(d[3])
                 : "r"(a0), "r"(a1), "r"(a2), "r"(a3), "r"(b0), "r"(b1));
}
__device__ __forceinline__ void cvt_hilo(float2 v, unsigned& hi, unsigned& lo) {
    __nv_bfloat162 h2 = __float22bfloat162_rn(v);
    float2 hf = __bfloat1622float2(h2);
    __nv_bfloat162 l2 = __float22bfloat162_rn(make_float2(v.x - hf.x, v.y - hf.y));
    hi = reinterpret_cast<unsigned&>(h2);
    lo = reinterpret_cast<unsigned&>(l2);
}

// ------- prep: x -> frag layout; h0 -> frag layout (slot 1); zero flags ----
__global__ void __launch_bounds__(256) prep_kernel(
    const float* __restrict__ x, const float* __restrict__ h0) {
    __shared__ float xs[16 * 260];
    const int bx  = blockIdx.x;
    const int tid = threadIdx.x;
    const int w    = tid >> 5;
    const int lane = tid & 31;
    const int rl   = lane >> 2;
    const int c2   = (lane & 3) * 2;
    const int mt  = bx >> 10;
    const int t   = bx & 1023;

    if (bx == 0 && tid < 128) ((int*)g_flagA)[tid] = 0;

    if (bx < 32) {                        // h0 -> g_hf[1]
        int tile = bx * 8 + w;
        int mth = tile >> 5, kc = tile & 31;
        const float* hb = h0 + (size_t)(mth * 16) * HHID + kc * 16;
        unsigned h0r,l0r,h1r,l1r,h2r,l2r,h3r,l3r;
        cvt_hilo(make_float2(hb[rl*HHID+c2],       hb[rl*HHID+c2+1]),       h0r,l0r);
        cvt_hilo(make_float2(hb[(rl+8)*HHID+c2],   hb[(rl+8)*HHID+c2+1]),   h1r,l1r);
        cvt_hilo(make_float2(hb[rl*HHID+c2+8],     hb[rl*HHID+c2+9]),       h2r,l2r);
        cvt_hilo(make_float2(hb[(rl+8)*HHID+c2+8], hb[(rl+8)*HHID+c2+9]),   h3r,l3r);
        g_hf[1][(size_t)tile * 64 + lane]      = make_uint4(h0r,h1r,h2r,h3r);
        g_hf[1][(size_t)tile * 64 + 32 + lane] = make_uint4(l0r,l1r,l2r,l3r);
    }

    #pragma unroll
    for (int it = 0; it < 16; it++)
        xs[it * 260 + tid] = x[(size_t)(mt * 16 + it) * TT * II + (size_t)t * II + tid];
    __syncthreads();

    #pragma unroll
    for (int sub = 0; sub < 2; sub++) {
        int ks = w * 2 + sub;
        int cb = ks * 16 + c2;
        unsigned h0r, l0r, h1r, l1r, h2r, l2r, h3r, l3r;
        cvt_hilo(make_float2(xs[rl * 260 + cb],           xs[rl * 260 + cb + 1]),       h0r, l0r);
        cvt_hilo(make_float2(xs[(rl + 8) * 260 + cb],     xs[(rl + 8) * 260 + cb + 1]), h1r, l1r);
        cvt_hilo(make_float2(xs[rl * 260 + cb + 8],       xs[rl * 260 + cb + 9]),       h2r, l2r);
        cvt_hilo(make_float2(xs[(rl + 8) * 260 + cb + 8], xs[(rl + 8) * 260 + cb + 9]), h3r, l3r);
        unsigned* dst = g_xf + (((size_t)mt * TT + t) * 16 + ks) * 256 + lane * 4;
        *(uint4*)dst         = make_uint4(h0r, h1r, h2r, h3r);
        *(uint4*)(dst + 128) = make_uint4(l0r, l1r, l2r, l3r);
    }
}

__global__ void __launch_bounds__(NTHREADS, 1) gru_mma(
    const float* __restrict__ h0,
    const float* __restrict__ Wih, const float* __restrict__ bih,
    const float* __restrict__ Whh, const float* __restrict__ bhh,
    float* __restrict__ out)
{
    extern __shared__ char smc[];
    __shared__ int sh_go;
    const int tid  = threadIdx.x;
    const int lane = tid & 31;
    const int w    = tid >> 5;
    const int grp  = blockIdx.x & 3;
    const int bm0  = grp * 32;
    const int cig  = blockIdx.x >> 2;        // = produced h chunk
    const int j0   = cig * 16;
    const int wm   = (w & 1) * 16;
    const int wn   = ((w >> 1) & 1) * 24;
    const int kw   = w >> 2;                 // K half (h and x)

    if (tid == 0) sh_go = 0;

    // ---- resident weights, bf16 hi/lo ----
    __nv_bfloat16* Whi_s = (__nv_bfloat16*)smc;
    __nv_bfloat16* Wlo_s = (__nv_bfloat16*)(smc + WLO);
    for (int idx = tid; idx < 48 * 768; idx += NTHREADS) {
        int n = idx / 768, k = idx - n * 768;
        int g = (n >> 4) * HHID + j0 + (n & 15);
        float v = (k < II) ? Wih[g * II + k] : Whh[g * HHID + (k - II)];
        __nv_bfloat16 hi = __float2bfloat16(v);
        Whi_s[n * WSTRIDE + k] = hi;
        Wlo_s[n * WSTRIDE + k] = __float2bfloat16(v - __bfloat162float(hi));
    }
    float* scrH0 = (float*)(smc + SCR0B);
    float* scrH1 = (float*)(smc + SCR1B);
    float* scrF  = (float*)(smc + SCRFB);
    float* bias  = (float*)(smc + BIASB);
    if (tid < 16) {
        int j = j0 + tid;
        bias[tid]      = bih[j]            + bhh[j];
        bias[16 + tid] = bih[HHID + j]     + bhh[HHID + j];
        bias[32 + tid] = bih[2 * HHID + j];
        bias[48 + tid] = bhh[2 * HHID + j];
    }
    __syncthreads();

    const uint32_t sb = smem_u32(smc);
    const int q  = lane & 7;
    const int mi = lane >> 3;
    const uint32_t a4base = sb + (uint32_t)(((wn + 8 * (mi >> 1) + q) * WSTRIDE
                                             + 8 * (mi & 1)) * 2);
    const uint32_t a2base = sb + (uint32_t)(((wn + 16 + q) * WSTRIDE
                                             + 8 * (mi & 1)) * 2);

#define CMPK(AH, AL, KB, ACC) {                                               \
    unsigned h0r,h1r,h2r,h3r,h4r,h5r,l0r,l1r,l2r,l3r,l4r,l5r;                 \
    ldsm4(a4base + (KB), h0r, h1r, h2r, h3r);                                 \
    ldsm2(a2base + (KB), h4r, h5r);                                           \
    ldsm4(a4base + WLO + (KB), l0r, l1r, l2r, l3r);                           \
    ldsm2(a2base + WLO + (KB), l4r, l5r);                                     \
    mma4(ACC[0], (AH).x,(AH).y,(AH).z,(AH).w, h0r, h1r);                      \
    mma4(ACC[1], (AH).x,(AH).y,(AH).z,(AH).w, h2r, h3r);                      \
    mma4(ACC[2], (AH).x,(AH).y,(AH).z,(AH).w, h4r, h5r);                      \
    mma4(ACC[0], (AH).x,(AH).y,(AH).z,(AH).w, l0r, l1r);                      \
    mma4(ACC[1], (AH).x,(AH).y,(AH).z,(AH).w, l2r, l3r);                      \
    mma4(ACC[2], (AH).x,(AH).y,(AH).z,(AH).w, l4r, l5r);                      \
    mma4(ACC[0], (AL).x,(AL).y,(AL).z,(AL).w, h0r, h1r);                      \
    mma4(ACC[1], (AL).x,(AL).y,(AL).z,(AL).w, h2r, h3r);                      \
    mma4(ACC[2], (AL).x,(AL).y,(AL).z,(AL).w, h4r, h5r); }

    const int mt2 = grp * 2 + (w & 1);           // this warp's A m-tile
    float* xpcA = g_xp + (size_t)(blockIdx.x * 2)     * TT * 1536;
    float* xpcB = g_xp + (size_t)(blockIdx.x * 2 + 1) * TT * 1536;
    float* xpcP = kw ? xpcB : xpcA;

    // -- x_proj tile for one t: this warp's (wm,wn) quarter, its K half --
#define XTILE(T8) {                                                           \
    const uint4* xb = (const uint4*)g_xf                                      \
                      + ((size_t)mt2 * TT + (T8)) * (16 * 64) + lane;         \
    float acc[3][4] = {{0,0,0,0},{0,0,0,0},{0,0,0,0}};                        \
    _Pragma("unroll")                                                         \
    for (int s = 0; s < 8; s++) {                                             \
        int ks = kw * 8 + s;                                                  \
        uint4 AH = xb[ks * 64];                                               \
        uint4 AL = xb[ks * 64 + 32];                                          \
        CMPK(AH, AL, (uint32_t)(ks * 32), acc);                               \
    }                                                                         \
    float* xpt = xpcP + (size_t)(T8) * 1536;                                  \
    _Pragma("unroll")                                                         \
    for (int nf = 0; nf < 3; nf++) {                                          \
        int n0 = wn + nf * 8 + (lane & 3) * 2;                                \
        int r0 = wm + (lane >> 2);                                            \
        *(float2*)(xpt + r0 * 48 + n0)       = make_float2(acc[nf][0], acc[nf][1]); \
        *(float2*)(xpt + (r0 + 8) * 48 + n0) = make_float2(acc[nf][2], acc[nf][3]); \
    } }

    // ---- prologue: seed x_proj for t = 0..XLOOK-1 ----
    for (int t8 = 0; t8 < XLOOK; t8++) { XTILE(t8); }
    __syncthreads();

    // ================= latency-critical scan (x folded in) ================
    const int mg  = (tid >> 4) * 2;
    const int jlg = tid & 15;
    float hprev[2];
    hprev[0] = h0[(bm0 + mg) * HHID + j0 + jlg];
    hprev[1] = h0[(bm0 + mg + 1) * HHID + j0 + jlg];

    const uint32_t HKB = (uint32_t)((II + kw * 256) * 2);
    volatile int* fl = (volatile int*)&g_flagA[grp][0];
    volatile int* go = (volatile int*)&sh_go;

    for (int t = 0; t < TT; t++) {
        const int pr = (t + 1) & 1;
        const int pw = t & 1;

        // -- x_proj gate operands (written >=8 steps ago; sync'd since) --
        const float* xptA = xpcA + (size_t)t * 1536;
        const float* xptB = xpcB + (size_t)t * 1536;
        float xg[2][3];
        #pragma unroll
        for (int i = 0; i < 2; i++) {
            xg[i][0] = xptA[(mg + i) * 48 + jlg]      + xptB[(mg + i) * 48 + jlg];
            xg[i][1] = xptA[(mg + i) * 48 + 16 + jlg] + xptB[(mg + i) * 48 + 16 + jlg];
            xg[i][2] = xptA[(mg + i) * 48 + 32 + jlg] + xptB[(mg + i) * 48 + 32 + jlg];
        }

        // -- readiness: warp 7 polls the 32 group flags, fans out via SMEM --
        if (w == 7) {
            int v;
            do { v = fl[lane]; } while (__any_sync(0xFFFFFFFFu, v < t));
            if (lane == 0) *go = t;
        }
        while (*go < t) { }

        // -- h A-frags: L2-coherent loads, pipelined depth 4 --
        const uint4* hfb = g_hf[pr] + ((size_t)mt2 * 32 + kw * 16) * 64 + lane;
        uint4 bufH[4], bufL[4];
        #pragma unroll
        for (int p = 0; p < 4; p++) {
            bufH[p] = __ldcg(hfb + p * 64);
            bufL[p] = __ldcg(hfb + p * 64 + 32);
        }
        float accA[3][4] = {{0,0,0,0},{0,0,0,0},{0,0,0,0}};
        float accB[3][4] = {{0,0,0,0},{0,0,0,0},{0,0,0,0}};
        #pragma unroll
        for (int ks = 0; ks < 16; ks++) {
            uint4 AH = bufH[ks & 3];
            uint4 AL = bufL[ks & 3];
            if (ks + 4 < 16) {
                bufH[ks & 3] = __ldcg(hfb + (ks + 4) * 64);
                bufL[ks & 3] = __ldcg(hfb + (ks + 4) * 64 + 32);
            }
            if (ks & 1) { CMPK(AH, AL, HKB + (uint32_t)(ks * 32), accB); }
            else        { CMPK(AH, AL, HKB + (uint32_t)(ks * 32), accA); }
        }
        {
            float* scr = kw ? scrH1 : scrH0;
            #pragma unroll
            for (int nf = 0; nf < 3; nf++) {
                int n0 = wn + nf * 8 + (lane & 3) * 2;
                int r0 = wm + (lane >> 2);
                scr[n0 * 33 + r0]           = accA[nf][0] + accB[nf][0];
                scr[(n0 + 1) * 33 + r0]     = accA[nf][1] + accB[nf][1];
                scr[n0 * 33 + r0 + 8]       = accA[nf][2] + accB[nf][2];
                scr[(n0 + 1) * 33 + r0 + 8] = accA[nf][3] + accB[nf][3];
            }
        }
        __syncthreads();

        // -- gates: thread owns (b = bm0+mg+i, j = j0+jlg) --
        #pragma unroll
        for (int i = 0; i < 2; i++) {
            int m = mg + i;
            float hr = scrH0[jlg * 33 + m]        + scrH1[jlg * 33 + m];
            float hz = scrH0[(16 + jlg) * 33 + m] + scrH1[(16 + jlg) * 33 + m];
            float hh = scrH0[(32 + jlg) * 33 + m] + scrH1[(32 + jlg) * 33 + m];
            float r  = 1.f / (1.f + __expf(-(xg[i][0] + hr + bias[jlg])));
            float z  = 1.f / (1.f + __expf(-(xg[i][1] + hz + bias[16 + jlg])));
            float n  = tanhf(xg[i][2] + bias[32 + jlg] + r * (hh + bias[48 + jlg]));
            float hn = (1.f - z) * n + z * hprev[i];
            hprev[i] = hn;
            scrF[jlg * 33 + m] = hn;
            if (t == TT - 1) {
                int o = (bm0 + m) * 2048 + j0 + jlg;
                out[o]                 = r;  out[o + 262144]        = r;
                out[o + 512]           = z;  out[o + 512 + 262144]  = z;
                out[o + 1024]          = n;  out[o + 1024 + 262144] = n;
                out[o + 1536]          = hn; out[o + 1536 + 262144] = hn;
            }
        }
        __syncthreads();

        // -- warps 0-1: build + publish new-h frags, release flag --
        if (t < TT - 1 && tid < 64) {
            int mtL = tid >> 5, ln = tid & 31;
            int rl2 = ln >> 2, c2b = (ln & 3) * 2;
            int rb  = mtL * 16 + rl2;
            unsigned fh0,fl0,fh1,fl1,fh2,fl2,fh3,fl3;
            cvt_hilo(make_float2(scrF[c2b * 33 + rb],       scrF[(c2b + 1) * 33 + rb]),     fh0, fl0);
            cvt_hilo(make_float2(scrF[c2b * 33 + rb + 8],   scrF[(c2b + 1) * 33 + rb + 8]), fh1, fl1);
            cvt_hilo(make_float2(scrF[(c2b + 8) * 33 + rb],     scrF[(c2b + 9) * 33 + rb]),     fh2, fl2);
            cvt_hilo(make_float2(scrF[(c2b + 8) * 33 + rb + 8], scrF[(c2b + 9) * 33 + rb + 8]), fh3, fl3);
            size_t base = ((size_t)(grp * 2 + mtL) * 32 + cig) * 64;
            g_hf[pw][base + ln]      = make_uint4(fh0, fh1, fh2, fh3);
            g_hf[pw][base + 32 + ln] = make_uint4(fl0, fl1, fl2, fl3);
            __threadfence();
            asm volatile("bar.sync 2, 64;" ::: "memory");
            if (tid == 0) ((volatile int*)&g_flagA[grp][cig])[0] = t + 1;
        }

        // -- x_proj tile for t+XLOOK: hides the exchange gap --
        if (t + XLOOK < TT) { XTILE(t + XLOOK); }
    }
    // flags reset by prep_kernel each launch
}

extern "C" void kernel_launch(void* const* d_in, const int* in_sizes, int n_in,
                              void* d_out, int out_size) {
    const float* x   = (const float*)d_in[0];
    const float* h   = (const float*)d_in[1];
    const float* Wih = (const float*)d_in[2];
    const float* bih = (const float*)d_in[3];
    const float* Whh = (const float*)d_in[4];
    const float* bhh = (const float*)d_in[5];
    float* out = (float*)d_out;

    prep_kernel<<<8192, 256>>>(x, h);

    cudaFuncSetAttribute(gru_mma, cudaFuncAttributeMaxDynamicSharedMemorySize,
                         SMEM_BYTES);
    gru_mma<<<GRID, NTHREADS, SMEM_BYTES>>>(h, Wih, bih, Whh, bhh, out);
}